// round 13
// baseline (speedup 1.0000x reference)
#include <cuda_runtime.h>
#include <cuda_bf16.h>
#include <cstdint>

// ---------------- problem constants ----------------
#define BB    2
#define SS    1024
#define LL    1024
#define DIMQ  2048
#define HH    16
#define KH    128
#define DC    512
#define DCQ   1536
#define RR    64

typedef __nv_bfloat16 bf16;

// ---------------- scratch (device globals, no allocs allowed) ----------------
#define DEVARR(name, n) __device__ __align__(256) bf16 name##_h[n]; __device__ __align__(256) bf16 name##_l[n];
DEVARR(s_hid,   BB * SS * DIMQ)
DEVARR(s_wq,    HH * KH * DIMQ)
DEVARR(s_wkcq,  HH * KH * DCQ)
DEVARR(s_wkckv, HH * KH * DC)
DEVARR(s_wqr,   HH * DCQ * RR)
DEVARR(s_wkr,   HH * DC * RR)
DEVARR(s_wo,    DIMQ * HH * KH)
DEVARR(s_qhk,   BB * SS * HH * KH)
DEVARR(s_qbig,  BB * SS * HH * DCQ)
DEVARR(s_kvr,   BB * LL * DC)
DEVARR(s_qr,    BB * HH * SS * RR)
DEVARR(s_kr,    BB * HH * LL * RR)
DEVARR(s_at,    BB * HH * SS * LL)
DEVARR(s_v,     BB * HH * LL * KH)
DEVARR(s_ctx,   BB * SS * HH * KH)
__device__ __align__(256) float g_qbig[BB * SS * HH * DCQ];
__device__ __align__(256) float g_sc  [BB * HH * SS * LL];
__device__ __align__(256) float2 g_tabq[SS * (DCQ / 2)];   // [pos][pair] (sin, cos)
__device__ __align__(256) float2 g_tabk[LL * (DC  / 2)];

// ---------------- helpers ----------------
__device__ __forceinline__ uint32_t smem_u32(const void* p) {
    uint32_t a;
    asm("{ .reg .u64 t; cvta.to.shared.u64 t, %1; cvt.u32.u64 %0, t; }" : "=r"(a) : "l"(p));
    return a;
}
__device__ __forceinline__ void ldsm4(uint32_t a, uint32_t* r) {
    asm volatile("ldmatrix.sync.aligned.m8n8.x4.shared.b16 {%0,%1,%2,%3}, [%4];"
        : "=r"(r[0]), "=r"(r[1]), "=r"(r[2]), "=r"(r[3]) : "r"(a));
}
__device__ __forceinline__ void ldsm4t(uint32_t a, uint32_t* r) {
    asm volatile("ldmatrix.sync.aligned.m8n8.x4.trans.shared.b16 {%0,%1,%2,%3}, [%4];"
        : "=r"(r[0]), "=r"(r[1]), "=r"(r[2]), "=r"(r[3]) : "r"(a));
}
__device__ __forceinline__ void mma_bf16(float* c, const uint32_t* a, const uint32_t* b) {
    asm volatile("mma.sync.aligned.m16n8k16.row.col.f32.bf16.bf16.f32 "
        "{%0,%1,%2,%3},{%4,%5,%6,%7},{%8,%9},{%0,%1,%2,%3};"
        : "+f"(c[0]), "+f"(c[1]), "+f"(c[2]), "+f"(c[3])
        : "r"(a[0]), "r"(a[1]), "r"(a[2]), "r"(a[3]), "r"(b[0]), "r"(b[1]));
}
// hi = RN bf16; lo = RN(x - hi)
__device__ __forceinline__ uint32_t pack_hi(float x, float y) {
    __nv_bfloat162 v = __floats2bfloat162_rn(x, y);
    return *reinterpret_cast<uint32_t*>(&v);
}
__device__ __forceinline__ uint32_t pack_lo(float x, float y) {
    float hx = __bfloat162float(__float2bfloat16_rn(x));
    float hy = __bfloat162float(__float2bfloat16_rn(y));
    __nv_bfloat162 v = __floats2bfloat162_rn(x - hx, y - hy);
    return *reinterpret_cast<uint32_t*>(&v);
}
// cp.async with L1 fill (.ca): co-resident CTA reuses shared B/weight tiles from L1
__device__ __forceinline__ void cpa16(uint32_t s, const void* g) {
    asm volatile("cp.async.ca.shared.global [%0], [%1], 16;" :: "r"(s), "l"(g));
}
#define CP_COMMIT() asm volatile("cp.async.commit_group;" ::: "memory")
#define CP_WAIT(n)  asm volatile("cp.async.wait_group %0;" :: "n"(n) : "memory")

// ---------------- bf16x3-split MMA GEMM ----------------
// C = A * (TB ? B^T : B); A = Ah+Al, B = Bh+Bl; 3 MMAs: AhBh + AlBh + AhBl.
// CTA 128 x BN x 32, 8 warps; 3 smem buffers (XOR-swizzled A / K-major B, no pad),
// 2 CTAs/SM, cp.async depth-2 pipeline: wait(1) per iter, no exposed gmem latency.
template<int BN, bool TB, bool SPLIT>
__global__ __launch_bounds__(256, 2)
void mma_gemm(const bf16* __restrict__ Ah, const bf16* __restrict__ Al,
              const bf16* __restrict__ Bh, const bf16* __restrict__ Bl,
              float* __restrict__ Cf, bf16* __restrict__ Ch, bf16* __restrict__ Cl,
              int Kd, int lda, int ldb, int ldc,
              long long aSb, long long aSh,
              long long bSb, long long bSh,
              long long cSb, long long cSh, int numH)
{
    constexpr int BM    = 128;
    constexpr int BK    = 32;
    constexpr int NF    = BN / 32;
    constexpr int ATILE = BM * BK;                    // XOR-swizzled, no pad (4096)
    constexpr int BST   = BN + 8;                     // only used when !TB
    constexpr int BTILE = TB ? (BN * BK) : (BK * BST);
    constexpr int BUFE  = 2 * ATILE + 2 * BTILE;
    constexpr int NP4   = BN / 4;
    constexpr int NCHB  = TB ? (BN * 4) : (BK * (BN / 8)); // 16B chunks per B array

    extern __shared__ bf16 sm[];

    const int z  = blockIdx.z;
    const int bb = z / numH;
    const int hh = z - bb * numH;
    const int m0 = blockIdx.y * BM;
    const int n0 = blockIdx.x * BN;
    Ah += bb * aSb + hh * aSh + (long long)m0 * lda;
    Al += bb * aSb + hh * aSh + (long long)m0 * lda;
    Bh += bb * bSb + hh * bSh;
    Bl += bb * bSb + hh * bSh;

    const int tid  = threadIdx.x;
    const int lane = tid & 31;
    const int w    = tid >> 5;
    const int wm   = w & 1;
    const int wn   = w >> 1;

    const uint32_t smb = smem_u32(sm);

    // ---- fragment addressing (XOR swizzle: chunk ^ ((row>>1)&3), 16B chunks) ----
    const int rowA = wm * 64 + (lane & 15);
    const int swA  = (rowA >> 1) & 3;
    const int chA  = lane >> 4;                 // +2*ks at use

    const int rowB = wn * NP4 + (lane & 7) + ((lane >> 4) << 3);   // TB=true
    const int swB  = (rowB >> 1) & 3;
    const int chB  = (lane >> 3) & 1;           // +2*ks at use

    const uint32_t bFragF = (uint32_t)((((lane & 7) + (((lane >> 3) & 1) << 3)) * BST
                                        + wn * NP4 + ((lane >> 4) << 3)) * 2);  // TB=false

    float acc[4][NF][4];
    #pragma unroll
    for (int i = 0; i < 4; i++)
        #pragma unroll
        for (int j = 0; j < NF; j++)
            #pragma unroll
            for (int q = 0; q < 4; q++) acc[i][j][q] = 0.f;

    auto issueLoads = [&](int it) {
        const int k0 = it * BK;
        const uint32_t base = smb + (uint32_t)((it % 3) * BUFE * 2);
        // A: 128 rows x 4 chunks, swizzled
        #pragma unroll
        for (int r = 0; r < 2; r++) {
            int c   = tid + r * 256;
            int row = c >> 2;
            int ch  = c & 3;
            int sw  = (row >> 1) & 3;
            uint32_t so = base + (uint32_t)((row * BK + ((ch ^ sw) << 3)) * 2);
            const long long go = (long long)row * lda + k0 + ch * 8;
            cpa16(so,                          Ah + go);
            cpa16(so + (uint32_t)(ATILE * 2),  Al + go);
        }
        const uint32_t bBase = base + (uint32_t)(2 * ATILE * 2);
        #pragma unroll
        for (int r = 0; r < NCHB / 256; r++) {
            int c = tid + r * 256;
            if (TB) {
                int row = c >> 2;
                int ch  = c & 3;
                int sw  = (row >> 1) & 3;
                uint32_t so = bBase + (uint32_t)((row * BK + ((ch ^ sw) << 3)) * 2);
                const long long go = (long long)(n0 + row) * ldb + k0 + ch * 8;
                cpa16(so,                          Bh + go);
                cpa16(so + (uint32_t)(BTILE * 2),  Bl + go);
            } else {
                int row = c / (BN / 8);
                int ch  = c % (BN / 8);
                uint32_t so = bBase + (uint32_t)((row * BST + ch * 8) * 2);
                const long long go = (long long)(k0 + row) * ldb + n0 + ch * 8;
                cpa16(so,                          Bh + go);
                cpa16(so + (uint32_t)(BTILE * 2),  Bl + go);
            }
        }
    };

    auto compute = [&](int it) {
        const uint32_t base = smb + (uint32_t)((it % 3) * BUFE * 2);
        const uint32_t aB = base;
        const uint32_t bB = base + (uint32_t)(2 * ATILE * 2);
        #pragma unroll
        for (int ks = 0; ks < 2; ks++) {
            // B fragments (held across the i-loop)
            uint32_t bh[NF][2], bl[NF][2];
            #pragma unroll
            for (int jj = 0; jj < NF / 2; jj++) {
                if (TB) {
                    uint32_t bd = bB + (uint32_t)(((rowB + jj * 16) * BK) * 2
                                                  + (((chB + 2 * ks) ^ swB) << 4));
                    ldsm4(bd, &bh[2 * jj][0]);
                    ldsm4(bd + (uint32_t)(BTILE * 2), &bl[2 * jj][0]);
                } else {
                    uint32_t bd = bB + bFragF + (uint32_t)((ks * 16) * BST * 2 + jj * 16 * 2);
                    ldsm4t(bd, &bh[2 * jj][0]);
                    ldsm4t(bd + (uint32_t)(BTILE * 2), &bl[2 * jj][0]);
                }
            }
            // A fragments: register double buffer
            uint32_t ah[2][4], al[2][4];
            {
                uint32_t ad = aB + (uint32_t)((rowA * BK) * 2 + (((chA + 2 * ks) ^ swA) << 4));
                ldsm4(ad, ah[0]);
                ldsm4(ad + (uint32_t)(ATILE * 2), al[0]);
            }
            #pragma unroll
            for (int i = 0; i < 4; i++) {
                const int cur = i & 1;
                if (i < 3) {
                    uint32_t ad = aB + (uint32_t)(((rowA + (i + 1) * 16) * BK) * 2
                                                  + (((chA + 2 * ks) ^ swA) << 4));
                    ldsm4(ad, ah[cur ^ 1]);
                    ldsm4(ad + (uint32_t)(ATILE * 2), al[cur ^ 1]);
                }
                #pragma unroll
                for (int j = 0; j < NF; j++) {
                    mma_bf16(acc[i][j], ah[cur], bh[j]);
                    mma_bf16(acc[i][j], al[cur], bh[j]);
                    mma_bf16(acc[i][j], ah[cur], bl[j]);
                }
            }
        }
    };

    const int nIter = Kd / BK;
    issueLoads(0);
    CP_COMMIT();
    if (nIter > 1) issueLoads(1);
    CP_COMMIT();
    for (int it = 0; it < nIter; ++it) {
        CP_WAIT(1);                 // load(it) complete (one group may remain in flight)
        __syncthreads();            // all warps see buf; compute(it-1) finished CTA-wide
        if (it + 2 < nIter) issueLoads(it + 2);   // buf[(it+2)%3] == buf[(it-1)%3], safe
        CP_COMMIT();                // empty group in tail iters keeps ordering exact
        compute(it);
    }

    // ---- epilogue ----
    const long long cOff = bb * cSb + hh * cSh;
    #pragma unroll
    for (int i = 0; i < 4; i++) {
        const int row = m0 + wm * 64 + i * 16 + (lane >> 2);
        #pragma unroll
        for (int j = 0; j < NF; j++) {
            const int col = n0 + wn * NP4 + j * 8 + (lane & 3) * 2;
            const long long o0 = cOff + (long long)row * ldc + col;
            const long long o1 = cOff + (long long)(row + 8) * ldc + col;
            if (SPLIT) {
                *(uint32_t*)&Ch[o0] = pack_hi(acc[i][j][0], acc[i][j][1]);
                *(uint32_t*)&Cl[o0] = pack_lo(acc[i][j][0], acc[i][j][1]);
                *(uint32_t*)&Ch[o1] = pack_hi(acc[i][j][2], acc[i][j][3]);
                *(uint32_t*)&Cl[o1] = pack_lo(acc[i][j][2], acc[i][j][3]);
            } else {
                *(float2*)&Cf[o0] = make_float2(acc[i][j][0], acc[i][j][1]);
                *(float2*)&Cf[o1] = make_float2(acc[i][j][2], acc[i][j][3]);
            }
        }
    }
}

// ---------------- sin/cos table build ----------------
__global__ void build_tab_kernel()
{
    const float LOG2_1E4 = 13.28771238f;
    int i = blockIdx.x * blockDim.x + threadIdx.x;
    const int NQ = SS * (DCQ / 2);
    const int NK = LL * (DC / 2);
    if (i < NQ) {
        int pos = i / (DCQ / 2), f = i % (DCQ / 2);
        float inv = exp2f(-LOG2_1E4 * (float)(2 * f) / (float)DCQ);
        float s, c;
        sincosf((float)pos * inv, &s, &c);
        g_tabq[i] = make_float2(s, c);
    } else if (i < NQ + NK) {
        int k = i - NQ;
        int pos = k / (DC / 2), f = k % (DC / 2);
        float inv = exp2f(-LOG2_1E4 * (float)(2 * f) / (float)DC);
        float s, c;
        sincosf((float)pos * inv, &s, &c);
        g_tabk[k] = make_float2(s, c);
    }
}

// ---------------- fused fp32 -> hi/lo bf16 split ----------------
__device__ __forceinline__ void split4(const float4* __restrict__ in,
                                       uint32_t* __restrict__ hi, uint32_t* __restrict__ lo, int i) {
    float4 v = in[i];
    hi[2 * i]     = pack_hi(v.x, v.y);
    hi[2 * i + 1] = pack_hi(v.z, v.w);
    lo[2 * i]     = pack_lo(v.x, v.y);
    lo[2 * i + 1] = pack_lo(v.z, v.w);
}

#define SZ4_HID   (BB * SS * DIMQ / 4)
#define SZ4_WQ    (HH * KH * DIMQ / 4)
#define SZ4_WKCQ  (HH * KH * DCQ / 4)
#define SZ4_WKCKV (HH * KH * DC / 4)
#define SZ4_WQR   (HH * DCQ * RR / 4)
#define SZ4_WKR   (HH * DC * RR / 4)
#define SZ4_WO    (DIMQ * HH * KH / 4)
#define OFF0 0
#define OFF1 (OFF0 + SZ4_HID)
#define OFF2 (OFF1 + SZ4_WQ)
#define OFF3 (OFF2 + SZ4_WKCQ)
#define OFF4 (OFF3 + SZ4_WKCKV)
#define OFF5 (OFF4 + SZ4_WQR)
#define OFF6 (OFF5 + SZ4_WKR)
#define OFF7 (OFF6 + SZ4_WO)

__global__ void fused_split_kernel(
    const float4* __restrict__ hid, const float4* __restrict__ wq,
    const float4* __restrict__ wkcq, const float4* __restrict__ wkckv,
    const float4* __restrict__ wqr, const float4* __restrict__ wkr,
    const float4* __restrict__ wo,
    uint32_t* __restrict__ hidh, uint32_t* __restrict__ hidl,
    uint32_t* __restrict__ wqh,  uint32_t* __restrict__ wql,
    uint32_t* __restrict__ wkcqh, uint32_t* __restrict__ wkcql,
    uint32_t* __restrict__ wkckvh, uint32_t* __restrict__ wkckvl,
    uint32_t* __restrict__ wqrh, uint32_t* __restrict__ wqrl,
    uint32_t* __restrict__ wkrh, uint32_t* __restrict__ wkrl,
    uint32_t* __restrict__ woh,  uint32_t* __restrict__ wol)
{
    int i = blockIdx.x * blockDim.x + threadIdx.x;
    if (i < OFF1)      split4(hid,   hidh,   hidl,   i - OFF0);
    else if (i < OFF2) split4(wq,    wqh,    wql,    i - OFF1);
    else if (i < OFF3) split4(wkcq,  wkcqh,  wkcql,  i - OFF2);
    else if (i < OFF4) split4(wkckv, wkckvh, wkckvl, i - OFF3);
    else if (i < OFF5) split4(wqr,   wqrh,   wqrl,   i - OFF4);
    else if (i < OFF6) split4(wkr,   wkrh,   wkrl,   i - OFF5);
    else if (i < OFF7) split4(wo,    woh,    wol,    i - OFF6);
}

// ---------------- RoPE (table-based) fused with split ----------------
__global__ void rope_split_kernel(const float* __restrict__ in,
                                  const float2* __restrict__ tab,
                                  uint32_t* __restrict__ oh, uint32_t* __restrict__ ol,
                                  long long total, int dim, int half,
                                  int posDiv, int posMod)
{
    long long t = (long long)blockIdx.x * blockDim.x + threadIdx.x;
    if (t >= total) return;
    const int q  = half >> 1;
    const int pi = (int)(t % q);
    const int j  = pi * 2;
    const long long r = t / q;
    const int pos = (int)((r / posDiv) % posMod);

    const float* p = in + r * (long long)dim;
    float x1a = p[j],        x1b = p[j + 1];
    float x2a = p[j + half], x2b = p[j + half + 1];

    const float2* trow = tab + (long long)pos * (dim / 2);
    float2 sc1 = trow[pi];
    float2 sc2 = trow[pi + dim / 4];

    float oa = x1a * sc1.y - x2a * sc1.x, ob = x1b * sc1.y - x2b * sc1.x;
    float pa = x2a * sc2.y + x1a * sc2.x, pb = x2b * sc2.y + x1b * sc2.x;

    long long b0 = (r * dim + j) >> 1;
    long long b1 = (r * dim + j + half) >> 1;
    oh[b0] = pack_hi(oa, ob);  ol[b0] = pack_lo(oa, ob);
    oh[b1] = pack_hi(pa, pb);  ol[b1] = pack_lo(pa, pb);
}

// ---------------- softmax (len 1024) fused with split ----------------
__global__ void softmax_kernel(const float* __restrict__ x,
                               uint32_t* __restrict__ oh, uint32_t* __restrict__ ol)
{
    const float4* p = (const float4*)(x + (long long)blockIdx.x * 1024);
    int tid  = threadIdx.x;
    int w    = tid >> 5;
    int lane = tid & 31;
    __shared__ float sha[8], shb[8];

    float4 v = p[tid];
    float m = fmaxf(fmaxf(v.x, v.y), fmaxf(v.z, v.w));
    #pragma unroll
    for (int o = 16; o > 0; o >>= 1) m = fmaxf(m, __shfl_xor_sync(0xffffffffu, m, o));
    if (lane == 0) sha[w] = m;
    __syncthreads();
    if (tid == 0) {
        float mm = sha[0];
        #pragma unroll
        for (int i = 1; i < 8; i++) mm = fmaxf(mm, sha[i]);
        sha[0] = mm;
    }
    __syncthreads();
    m = sha[0];

    v.x = __expf(v.x - m);
    v.y = __expf(v.y - m);
    v.z = __expf(v.z - m);
    v.w = __expf(v.w - m);
    float s = v.x + v.y + v.z + v.w;
    #pragma unroll
    for (int o = 16; o > 0; o >>= 1) s += __shfl_xor_sync(0xffffffffu, s, o);
    if (lane == 0) shb[w] = s;
    __syncthreads();
    if (tid == 0) {
        float ss = 0.f;
        #pragma unroll
        for (int i = 0; i < 8; i++) ss += shb[i];
        shb[0] = ss;
    }
    __syncthreads();
    float inv = 1.f / shb[0];
    v.x *= inv; v.y *= inv; v.z *= inv; v.w *= inv;

    long long base = ((long long)blockIdx.x * 1024 + tid * 4) >> 1;
    oh[base]     = pack_hi(v.x, v.y);
    oh[base + 1] = pack_hi(v.z, v.w);
    ol[base]     = pack_lo(v.x, v.y);
    ol[base + 1] = pack_lo(v.z, v.w);
}

// ---------------- launch ----------------
static inline void set_smem(const void* fn, int bytes) {
    cudaFuncSetAttribute(fn, cudaFuncAttributeMaxDynamicSharedMemorySize, bytes);
}

#define GETSYM(var, sym) cudaGetSymbolAddress((void**)&var, sym)

extern "C" void kernel_launch(void* const* d_in, const int* in_sizes, int n_in,
                              void* d_out, int out_size)
{
    const float* hidden  = (const float*)d_in[0];
    const float* kv_c    = (const float*)d_in[1];
    const float* Wq      = (const float*)d_in[2];
    const float* w_kc_q  = (const float*)d_in[3];
    const float* w_kc_kv = (const float*)d_in[4];
    const float* W_qr    = (const float*)d_in[5];
    const float* W_kr    = (const float*)d_in[6];
    const float* Wo      = (const float*)d_in[7];
    float* out = (float*)d_out;

    bf16 *hidh, *hidl, *wqh, *wql, *wkcqh, *wkcql, *wkckvh, *wkckvl;
    bf16 *wqrh, *wqrl, *wkrh, *wkrl, *woh, *wol;
    bf16 *qhkh, *qhkl, *qbh, *qbl, *kvrh, *kvrl, *qrh, *qrl, *krh, *krl;
    bf16 *ath, *atl, *vh, *vl, *ctxh, *ctxl;
    float *qbigf, *scf;
    float2 *tabq, *tabk;

    GETSYM(hidh, s_hid_h);     GETSYM(hidl, s_hid_l);
    GETSYM(wqh, s_wq_h);       GETSYM(wql, s_wq_l);
    GETSYM(wkcqh, s_wkcq_h);   GETSYM(wkcql, s_wkcq_l);
    GETSYM(wkckvh, s_wkckv_h); GETSYM(wkckvl, s_wkckv_l);
    GETSYM(wqrh, s_wqr_h);     GETSYM(wqrl, s_wqr_l);
    GETSYM(wkrh, s_wkr_h);     GETSYM(wkrl, s_wkr_l);
    GETSYM(woh, s_wo_h);       GETSYM(wol, s_wo_l);
    GETSYM(qhkh, s_qhk_h);     GETSYM(qhkl, s_qhk_l);
    GETSYM(qbh, s_qbig_h);     GETSYM(qbl, s_qbig_l);
    GETSYM(kvrh, s_kvr_h);     GETSYM(kvrl, s_kvr_l);
    GETSYM(qrh, s_qr_h);       GETSYM(qrl, s_qr_l);
    GETSYM(krh, s_kr_h);       GETSYM(krl, s_kr_l);
    GETSYM(ath, s_at_h);       GETSYM(atl, s_at_l);
    GETSYM(vh, s_v_h);         GETSYM(vl, s_v_l);
    GETSYM(ctxh, s_ctx_h);     GETSYM(ctxl, s_ctx_l);
    GETSYM(qbigf, g_qbig);     GETSYM(scf, g_sc);
    GETSYM(tabq, g_tabq);      GETSYM(tabk, g_tabk);

    const int MS = BB * SS;
    // dynamic smem per CTA: 3 buffers x (2*A + 2*B) bf16 tiles (2 CTAs/SM)
    const int SM_T128 = 3 * (2 * 4096 + 2 * 4096) * 2;            // 98304
    const int SM_F128 = 3 * (2 * 4096 + 2 * 32 * 136) * 2;        // 101376
    const int SM_F64  = 3 * (2 * 4096 + 2 * 32 * 72) * 2;         // 76800

    set_smem((const void*)mma_gemm<128, true,  true>,  SM_T128);
    set_smem((const void*)mma_gemm<128, true,  false>, SM_T128);
    set_smem((const void*)mma_gemm<128, false, true>,  SM_F128);
    set_smem((const void*)mma_gemm<128, false, false>, SM_F128);
    set_smem((const void*)mma_gemm<64,  false, true>,  SM_F64);

    // [0] sin/cos tables
    {
        int total = SS * (DCQ / 2) + LL * (DC / 2);
        build_tab_kernel<<<(total + 255) / 256, 256>>>();
    }

    // [1] fused operand split
    fused_split_kernel<<<OFF7 / 256, 256>>>(
        (const float4*)hidden, (const float4*)Wq, (const float4*)w_kc_q,
        (const float4*)w_kc_kv, (const float4*)W_qr, (const float4*)W_kr,
        (const float4*)Wo,
        (uint32_t*)hidh, (uint32_t*)hidl, (uint32_t*)wqh, (uint32_t*)wql,
        (uint32_t*)wkcqh, (uint32_t*)wkcql, (uint32_t*)wkckvh, (uint32_t*)wkckvl,
        (uint32_t*)wqrh, (uint32_t*)wqrl, (uint32_t*)wkrh, (uint32_t*)wkrl,
        (uint32_t*)woh, (uint32_t*)wol);

    // [2] q_hk = hidden @ Wq^T  -> split out
    mma_gemm<128, true, true><<<dim3(DIMQ/128, MS/128, 1), 256, SM_T128>>>(
        hidh, hidl, wqh, wql, nullptr, qhkh, qhkl,
        DIMQ, DIMQ, DIMQ, HH*KH,
        0, 0, 0, 0, 0, 0, 1);

    // [3] q_big = q_hk[h-slice] @ w_kc_q[h]  -> fp32 (pre-RoPE)
    mma_gemm<128, false, false><<<dim3(DCQ/128, MS/128, HH), 256, SM_F128>>>(
        qhkh, qhkl, wkcqh, wkcql, qbigf, nullptr, nullptr,
        KH, HH*KH, DCQ, HH*DCQ,
        0, KH,
        0, (long long)KH*DCQ,
        0, DCQ,
        HH);

    // [4] RoPE+split q_big (table)
    {
        long long total = (long long)BB * SS * HH * (DCQ / 4);
        rope_split_kernel<<<(unsigned)((total + 255) / 256), 256>>>(
            qbigf, tabq, (uint32_t*)qbh, (uint32_t*)qbl, total, DCQ, DCQ/2, HH, SS);
    }
    // [5] RoPE+split kv_c -> kvr (table)
    {
        long long total = (long long)BB * LL * (DC / 4);
        rope_split_kernel<<<(unsigned)((total + 255) / 256), 256>>>(
            kv_c, tabk, (uint32_t*)kvrh, (uint32_t*)kvrl, total, DC, DC/2, 1, LL);
    }

    // [6] V[b,h] = kvr[b] @ w_kc_kv[h]^T  -> split out
    mma_gemm<128, true, true><<<dim3(1, LL/128, BB*HH), 256, SM_T128>>>(
        kvrh, kvrl, wkckvh, wkckvl, nullptr, vh, vl,
        DC, DC, DC, KH,
        (long long)LL*DC, 0,
        0, (long long)KH*DC,
        (long long)HH*LL*KH, (long long)LL*KH,
        HH);

    // [7] q_r = q_big[b,:,h,:] @ W_qr[h]  -> split out
    mma_gemm<64, false, true><<<dim3(1, SS/128, BB*HH), 256, SM_F64>>>(
        qbh, qbl, wqrh, wqrl, nullptr, qrh, qrl,
        DCQ, HH*DCQ, RR, RR,
        (long long)SS*HH*DCQ, DCQ,
        0, (long long)DCQ*RR,
        (long long)HH*SS*RR, (long long)SS*RR,
        HH);

    // [8] k_r = kvr[b] @ W_kr[h]  -> split out
    mma_gemm<64, false, true><<<dim3(1, LL/128, BB*HH), 256, SM_F64>>>(
        kvrh, kvrl, wkrh, wkrl, nullptr, krh, krl,
        DC, DC, RR, RR,
        (long long)LL*DC, 0,
        0, (long long)DC*RR,
        (long long)HH*LL*RR, (long long)LL*RR,
        HH);

    // [9] scores = q_r @ k_r^T  -> fp32 (pre-softmax)
    mma_gemm<128, true, false><<<dim3(LL/128, SS/128, BB*HH), 256, SM_T128>>>(
        qrh, qrl, krh, krl, scf, nullptr, nullptr,
        RR, RR, RR, LL,
        (long long)HH*SS*RR, (long long)SS*RR,
        (long long)HH*LL*RR, (long long)LL*RR,
        (long long)HH*SS*LL, (long long)SS*LL,
        HH);

    // [10] softmax + split
    softmax_kernel<<<BB*HH*SS, 256>>>(scf, (uint32_t*)ath, (uint32_t*)atl);

    // [11] ctx[b,s,h*K:] = attn[b,h] @ V[b,h]  -> split out
    mma_gemm<128, false, true><<<dim3(1, SS/128, BB*HH), 256, SM_F128>>>(
        ath, atl, vh, vl, nullptr, ctxh, ctxl,
        LL, LL, KH, HH*KH,
        (long long)HH*SS*LL, (long long)SS*LL,
        (long long)HH*LL*KH, (long long)LL*KH,
        (long long)SS*HH*KH, KH,
        HH);

    // [12] out = ctx @ Wo^T  -> fp32 final
    mma_gemm<128, true, false><<<dim3(DIMQ/128, MS/128, 1), 256, SM_T128>>>(
        ctxh, ctxl, woh, wol, out, nullptr, nullptr,
        HH*KH, HH*KH, HH*KH, DIMQ,
        0, 0, 0, 0, 0, 0, 1);
}

// round 14
// speedup vs baseline: 1.1701x; 1.1701x over previous
#include <cuda_runtime.h>
#include <cuda_bf16.h>
#include <cstdint>

// ---------------- problem constants ----------------
#define BB    2
#define SS    1024
#define LL    1024
#define DIMQ  2048
#define HH    16
#define KH    128
#define DC    512
#define DCQ   1536
#define RR    64

typedef __nv_bfloat16 bf16;

// ---------------- scratch (device globals, no allocs allowed) ----------------
#define DEVARR(name, n) __device__ __align__(256) bf16 name##_h[n]; __device__ __align__(256) bf16 name##_l[n];
DEVARR(s_hid,   BB * SS * DIMQ)
DEVARR(s_wq,    HH * KH * DIMQ)
DEVARR(s_wkcq,  HH * KH * DCQ)
DEVARR(s_wkckv, HH * KH * DC)
DEVARR(s_wqr,   HH * DCQ * RR)
DEVARR(s_wkr,   HH * DC * RR)
DEVARR(s_wo,    DIMQ * HH * KH)
DEVARR(s_qhk,   BB * SS * HH * KH)
DEVARR(s_qbig,  BB * SS * HH * DCQ)
DEVARR(s_kvr,   BB * LL * DC)
DEVARR(s_qr,    BB * HH * SS * RR)
DEVARR(s_kr,    BB * HH * LL * RR)
DEVARR(s_v,     BB * HH * LL * KH)
DEVARR(s_ctx,   BB * SS * HH * KH)
__device__ __align__(256) float g_qbig[BB * SS * HH * DCQ];
__device__ __align__(256) float2 g_tabq[SS * (DCQ / 2)];   // [pos][pair] (sin, cos)
__device__ __align__(256) float2 g_tabk[LL * (DC  / 2)];

// ---------------- helpers ----------------
__device__ __forceinline__ uint32_t smem_u32(const void* p) {
    uint32_t a;
    asm("{ .reg .u64 t; cvta.to.shared.u64 t, %1; cvt.u32.u64 %0, t; }" : "=r"(a) : "l"(p));
    return a;
}
__device__ __forceinline__ void ldsm4(uint32_t a, uint32_t* r) {
    asm volatile("ldmatrix.sync.aligned.m8n8.x4.shared.b16 {%0,%1,%2,%3}, [%4];"
        : "=r"(r[0]), "=r"(r[1]), "=r"(r[2]), "=r"(r[3]) : "r"(a));
}
__device__ __forceinline__ void ldsm4t(uint32_t a, uint32_t* r) {
    asm volatile("ldmatrix.sync.aligned.m8n8.x4.trans.shared.b16 {%0,%1,%2,%3}, [%4];"
        : "=r"(r[0]), "=r"(r[1]), "=r"(r[2]), "=r"(r[3]) : "r"(a));
}
__device__ __forceinline__ void mma_bf16(float* c, const uint32_t* a, const uint32_t* b) {
    asm volatile("mma.sync.aligned.m16n8k16.row.col.f32.bf16.bf16.f32 "
        "{%0,%1,%2,%3},{%4,%5,%6,%7},{%8,%9},{%0,%1,%2,%3};"
        : "+f"(c[0]), "+f"(c[1]), "+f"(c[2]), "+f"(c[3])
        : "r"(a[0]), "r"(a[1]), "r"(a[2]), "r"(a[3]), "r"(b[0]), "r"(b[1]));
}
// hi = RN bf16; lo = RN(x - hi)
__device__ __forceinline__ uint32_t pack_hi(float x, float y) {
    __nv_bfloat162 v = __floats2bfloat162_rn(x, y);
    return *reinterpret_cast<uint32_t*>(&v);
}
__device__ __forceinline__ uint32_t pack_lo(float x, float y) {
    float hx = __bfloat162float(__float2bfloat16_rn(x));
    float hy = __bfloat162float(__float2bfloat16_rn(y));
    __nv_bfloat162 v = __floats2bfloat162_rn(x - hx, y - hy);
    return *reinterpret_cast<uint32_t*>(&v);
}
__device__ __forceinline__ void cpa16(uint32_t s, const void* g) {
    asm volatile("cp.async.ca.shared.global [%0], [%1], 16;" :: "r"(s), "l"(g));
}
#define CP_COMMIT() asm volatile("cp.async.commit_group;" ::: "memory")
#define CP_WAIT(n)  asm volatile("cp.async.wait_group %0;" :: "n"(n) : "memory")

// ---------------- bf16x3-split MMA GEMM (R9/R10 proven config) ----------------
template<int BN, bool TB, bool SPLIT>
__global__ __launch_bounds__(256, 2)
void mma_gemm(const bf16* __restrict__ Ah, const bf16* __restrict__ Al,
              const bf16* __restrict__ Bh, const bf16* __restrict__ Bl,
              float* __restrict__ Cf, bf16* __restrict__ Ch, bf16* __restrict__ Cl,
              int Kd, int lda, int ldb, int ldc,
              long long aSb, long long aSh,
              long long bSb, long long bSh,
              long long cSb, long long cSh, int numH)
{
    constexpr int BM    = 128;
    constexpr int BK    = 32;
    constexpr int NF    = BN / 32;
    constexpr int AST   = BK + 8;
    constexpr int ATILE = BM * AST;
    constexpr int BROWS = TB ? BN : BK;
    constexpr int BST   = TB ? (BK + 8) : (BN + 8);
    constexpr int BTILE = BROWS * BST;
    constexpr int BUFE  = 2 * ATILE + 2 * BTILE;
    constexpr int NP4   = BN / 4;
    constexpr int NCHB  = TB ? (BN * 4) : (32 * (BN / 8));

    extern __shared__ bf16 sm[];

    const int z  = blockIdx.z;
    const int bb = z / numH;
    const int hh = z - bb * numH;
    const int m0 = blockIdx.y * BM;
    const int n0 = blockIdx.x * BN;
    Ah += bb * aSb + hh * aSh + (long long)m0 * lda;
    Al += bb * aSb + hh * aSh + (long long)m0 * lda;
    Bh += bb * bSb + hh * bSh;
    Bl += bb * bSb + hh * bSh;

    const int tid  = threadIdx.x;
    const int lane = tid & 31;
    const int w    = tid >> 5;
    const int wm   = w & 1;
    const int wn   = w >> 1;

    const uint32_t smb = smem_u32(sm);

    const uint32_t aFrag = (uint32_t)(((wm * 64 + (lane & 15)) * AST + ((lane >> 4) << 3)) * 2);
    uint32_t bFrag;
    if (TB)
        bFrag = (uint32_t)(((wn * NP4 + (lane & 7) + ((lane >> 4) << 3)) * BST
                            + (((lane >> 3) & 1) << 3)) * 2);
    else
        bFrag = (uint32_t)((((lane & 7) + (((lane >> 3) & 1) << 3)) * BST
                            + wn * NP4 + ((lane >> 4) << 3)) * 2);

    float acc[4][NF][4];
    #pragma unroll
    for (int i = 0; i < 4; i++)
        #pragma unroll
        for (int j = 0; j < NF; j++)
            #pragma unroll
            for (int q = 0; q < 4; q++) acc[i][j][q] = 0.f;

    auto issueLoads = [&](int it) {
        const int k0 = it * BK;
        const uint32_t base = smb + (uint32_t)((it & 1) * BUFE * 2);
        #pragma unroll
        for (int r = 0; r < 2; r++) {
            int c   = tid + r * 256;
            int row = c >> 2;
            int ch  = c & 3;
            uint32_t so = base + (uint32_t)((row * AST + ch * 8) * 2);
            const long long go = (long long)row * lda + k0 + ch * 8;
            cpa16(so,                          Ah + go);
            cpa16(so + (uint32_t)(ATILE * 2),  Al + go);
        }
        const uint32_t bBase = base + (uint32_t)(2 * ATILE * 2);
        #pragma unroll
        for (int r = 0; r < NCHB / 256; r++) {
            int c = tid + r * 256;
            int row, ch;
            long long go;
            if (TB) {
                row = c >> 2; ch = c & 3;
                go = (long long)(n0 + row) * ldb + k0 + ch * 8;
            } else {
                row = c / (BN / 8); ch = c % (BN / 8);
                go = (long long)(k0 + row) * ldb + n0 + ch * 8;
            }
            uint32_t so = bBase + (uint32_t)((row * BST + ch * 8) * 2);
            cpa16(so,                          Bh + go);
            cpa16(so + (uint32_t)(BTILE * 2),  Bl + go);
        }
    };

    auto compute = [&](int it) {
        const uint32_t base = smb + (uint32_t)((it & 1) * BUFE * 2);
        const uint32_t aB = base;
        const uint32_t bB = base + (uint32_t)(2 * ATILE * 2);
        #pragma unroll
        for (int ks = 0; ks < 2; ks++) {
            uint32_t bh[NF][2], bl[NF][2];
            #pragma unroll
            for (int jj = 0; jj < NF / 2; jj++) {
                uint32_t bd;
                if (TB) {
                    bd = bB + bFrag + (uint32_t)((ks * 16) * 2 + jj * (16 * BST * 2));
                    ldsm4(bd, &bh[2 * jj][0]);
                    ldsm4(bd + (uint32_t)(BTILE * 2), &bl[2 * jj][0]);
                } else {
                    bd = bB + bFrag + (uint32_t)((ks * 16) * BST * 2 + jj * (16 * 2));
                    ldsm4t(bd, &bh[2 * jj][0]);
                    ldsm4t(bd + (uint32_t)(BTILE * 2), &bl[2 * jj][0]);
                }
            }
            uint32_t ah[2][4], al[2][4];
            {
                uint32_t ad = aB + aFrag + (uint32_t)((ks * 16) * 2);
                ldsm4(ad, ah[0]);
                ldsm4(ad + (uint32_t)(ATILE * 2), al[0]);
            }
            #pragma unroll
            for (int i = 0; i < 4; i++) {
                const int cur = i & 1;
                if (i < 3) {
                    uint32_t ad = aB + aFrag + (uint32_t)((ks * 16) * 2 + (i + 1) * (16 * AST * 2));
                    ldsm4(ad, ah[cur ^ 1]);
                    ldsm4(ad + (uint32_t)(ATILE * 2), al[cur ^ 1]);
                }
                #pragma unroll
                for (int j = 0; j < NF; j++) {
                    mma_bf16(acc[i][j], ah[cur], bh[j]);
                    mma_bf16(acc[i][j], al[cur], bh[j]);
                    mma_bf16(acc[i][j], ah[cur], bl[j]);
                }
            }
        }
    };

    const int nIter = Kd / BK;
    issueLoads(0);
    CP_COMMIT();
    for (int it = 0; it < nIter; ++it) {
        CP_WAIT(0);
        __syncthreads();
        if (it + 1 < nIter) {
            issueLoads(it + 1);
            CP_COMMIT();
        }
        compute(it);
    }

    const long long cOff = bb * cSb + hh * cSh;
    #pragma unroll
    for (int i = 0; i < 4; i++) {
        const int row = m0 + wm * 64 + i * 16 + (lane >> 2);
        #pragma unroll
        for (int j = 0; j < NF; j++) {
            const int col = n0 + wn * NP4 + j * 8 + (lane & 3) * 2;
            const long long o0 = cOff + (long long)row * ldc + col;
            const long long o1 = cOff + (long long)(row + 8) * ldc + col;
            if (SPLIT) {
                *(uint32_t*)&Ch[o0] = pack_hi(acc[i][j][0], acc[i][j][1]);
                *(uint32_t*)&Cl[o0] = pack_lo(acc[i][j][0], acc[i][j][1]);
                *(uint32_t*)&Ch[o1] = pack_hi(acc[i][j][2], acc[i][j][3]);
                *(uint32_t*)&Cl[o1] = pack_lo(acc[i][j][2], acc[i][j][3]);
            } else {
                *(float2*)&Cf[o0] = make_float2(acc[i][j][0], acc[i][j][1]);
                *(float2*)&Cf[o1] = make_float2(acc[i][j][2], acc[i][j][3]);
            }
        }
    }
}

// ---------------- fused flash attention: scores + softmax + attn@V ----------------
// Per CTA: 128 S-rows of one (b,h). 8 warps, 16 rows each. Q-frags in registers.
// Loop 16 L-tiles of 64: S = Q@K^T (3-term), online softmax, O += P@V (3-term).
// smem: Q [128][72] h/l (36864 B) + 2 buffers x (K [64][72] h/l + V [64][136] h/l) (53248 B each).
#define FL_SMEM 143360
__global__ __launch_bounds__(256, 1)
void flash_kernel(const bf16* __restrict__ Qh, const bf16* __restrict__ Ql,
                  const bf16* __restrict__ Kh, const bf16* __restrict__ Kl,
                  const bf16* __restrict__ Vh, const bf16* __restrict__ Vl,
                  bf16* __restrict__ Ch, bf16* __restrict__ Cl)
{
    extern __shared__ bf16 fsm[];
    const uint32_t smb = smem_u32(fsm);
    const uint32_t QHO = 0, QLO = 18432;           // byte offsets
    // buffer base = 36864 + buf*53248; K_h +0, K_l +9216, V_h +18432, V_l +35840

    const int st = blockIdx.x;          // s-tile 0..7
    const int bh = blockIdx.y;          // b*16+h
    const int b  = bh >> 4;
    const int h  = bh & 15;
    const int tid = threadIdx.x, lane = tid & 31, w = tid >> 5;

    const bf16* qh = Qh + ((long long)bh * SS + st * 128) * RR;
    const bf16* ql = Ql + ((long long)bh * SS + st * 128) * RR;
    const bf16* kh = Kh + (long long)bh * LL * RR;
    const bf16* kl = Kl + (long long)bh * LL * RR;
    const bf16* vh = Vh + (long long)bh * LL * KH;
    const bf16* vl = Vl + (long long)bh * LL * KH;

    // ---- stage Q (128 x 64 h/l) into dedicated smem region ----
    #pragma unroll
    for (int r = 0; r < 4; r++) {
        int c = tid + r * 256;              // 1024 chunks
        int row = c >> 3, ch = c & 7;
        uint32_t so = smb + QHO + (uint32_t)((row * 72 + ch * 8) * 2);
        cpa16(so,                 qh + row * 64 + ch * 8);
        cpa16(so + (QLO - QHO),   ql + row * 64 + ch * 8);
    }
    CP_COMMIT();
    CP_WAIT(0);
    __syncthreads();

    // Q A-fragments (rows w*16..+15, K=64 -> 4 k-frags), hi and lo
    uint32_t qfh[4][4], qfl[4][4];
    #pragma unroll
    for (int ks = 0; ks < 4; ks++) {
        uint32_t ad = smb + QHO + (uint32_t)(((w * 16 + (lane & 15)) * 72 + ks * 16 + ((lane >> 4) << 3)) * 2);
        ldsm4(ad, qfh[ks]);
        ldsm4(ad + (QLO - QHO), qfl[ks]);
    }

    float oacc[16][4];
    #pragma unroll
    for (int j = 0; j < 16; j++)
        #pragma unroll
        for (int q = 0; q < 4; q++) oacc[j][q] = 0.f;
    float rmax[2] = {-1e30f, -1e30f};
    float rsum[2] = {0.f, 0.f};

    auto issueTile = [&](int lt) {
        const uint32_t base = smb + 36864u + (uint32_t)((lt & 1) * 53248);
        #pragma unroll
        for (int r = 0; r < 2; r++) {           // K: 512 chunks per array
            int c = tid + r * 256;
            int row = c >> 3, ch = c & 7;
            uint32_t so = base + (uint32_t)((row * 72 + ch * 8) * 2);
            const long long go = (long long)(lt * 64 + row) * 64 + ch * 8;
            cpa16(so,          kh + go);
            cpa16(so + 9216u,  kl + go);
        }
        #pragma unroll
        for (int r = 0; r < 4; r++) {           // V: 1024 chunks per array
            int c = tid + r * 256;
            int row = c >> 4, ch = c & 15;
            uint32_t so = base + 18432u + (uint32_t)((row * 136 + ch * 8) * 2);
            const long long go = (long long)(lt * 64 + row) * 128 + ch * 8;
            cpa16(so,           vh + go);
            cpa16(so + 17408u,  vl + go);
        }
    };

    issueTile(0);
    CP_COMMIT();

    for (int lt = 0; lt < 16; ++lt) {
        CP_WAIT(0);
        __syncthreads();                        // tile lt visible; compute(lt-1) done CTA-wide
        if (lt + 1 < 16) {
            issueTile(lt + 1);                  // overwrites buf[(lt+1)&1] (done at barrier)
            CP_COMMIT();
        }

        const uint32_t base = smb + 36864u + (uint32_t)((lt & 1) * 53248);
        const uint32_t kB = base;
        const uint32_t vB = base + 18432u;

        // ---- S = Q @ K^T  (64 cols = 8 n-frags) ----
        float sacc[8][4];
        #pragma unroll
        for (int j = 0; j < 8; j++)
            #pragma unroll
            for (int q = 0; q < 4; q++) sacc[j][q] = 0.f;

        #pragma unroll
        for (int ks = 0; ks < 4; ks++) {
            #pragma unroll
            for (int jj = 0; jj < 4; jj++) {
                uint32_t b4h[4], b4l[4];
                uint32_t bd = kB + (uint32_t)(((jj * 16 + (lane & 7) + ((lane >> 4) << 3)) * 72
                                              + ks * 16 + (((lane >> 3) & 1) << 3)) * 2);
                ldsm4(bd, b4h);
                ldsm4(bd + 9216u, b4l);
                #pragma unroll
                for (int t = 0; t < 2; t++) {
                    const int j = 2 * jj + t;
                    mma_bf16(sacc[j], qfh[ks], &b4h[2 * t]);
                    mma_bf16(sacc[j], qfl[ks], &b4h[2 * t]);
                    mma_bf16(sacc[j], qfh[ks], &b4l[2 * t]);
                }
            }
        }

        // ---- online softmax (two row-halves per thread) ----
        #pragma unroll
        for (int p = 0; p < 2; p++) {
            float tmax = -1e30f;
            #pragma unroll
            for (int j = 0; j < 8; j++)
                tmax = fmaxf(tmax, fmaxf(sacc[j][2 * p], sacc[j][2 * p + 1]));
            tmax = fmaxf(tmax, __shfl_xor_sync(0xffffffffu, tmax, 1));
            tmax = fmaxf(tmax, __shfl_xor_sync(0xffffffffu, tmax, 2));
            float mnew = fmaxf(rmax[p], tmax);
            float sc = __expf(rmax[p] - mnew);
            rmax[p] = mnew;
            float tsum = 0.f;
            #pragma unroll
            for (int j = 0; j < 8; j++) {
                float e0 = __expf(sacc[j][2 * p]     - mnew);
                float e1 = __expf(sacc[j][2 * p + 1] - mnew);
                sacc[j][2 * p] = e0; sacc[j][2 * p + 1] = e1;
                tsum += e0 + e1;
            }
            tsum += __shfl_xor_sync(0xffffffffu, tsum, 1);
            tsum += __shfl_xor_sync(0xffffffffu, tsum, 2);
            rsum[p] = rsum[p] * sc + tsum;
            #pragma unroll
            for (int j = 0; j < 16; j++) {
                oacc[j][2 * p]     *= sc;
                oacc[j][2 * p + 1] *= sc;
            }
        }

        // ---- O += P @ V  (P C-frags -> A-frags, split hi/lo) ----
        #pragma unroll
        for (int kf = 0; kf < 4; kf++) {
            uint32_t ph[4], pl[4];
            ph[0] = pack_hi(sacc[2 * kf][0],     sacc[2 * kf][1]);
            ph[1] = pack_hi(sacc[2 * kf][2],     sacc[2 * kf][3]);
            ph[2] = pack_hi(sacc[2 * kf + 1][0], sacc[2 * kf + 1][1]);
            ph[3] = pack_hi(sacc[2 * kf + 1][2], sacc[2 * kf + 1][3]);
            pl[0] = pack_lo(sacc[2 * kf][0],     sacc[2 * kf][1]);
            pl[1] = pack_lo(sacc[2 * kf][2],     sacc[2 * kf][3]);
            pl[2] = pack_lo(sacc[2 * kf + 1][0], sacc[2 * kf + 1][1]);
            pl[3] = pack_lo(sacc[2 * kf + 1][2], sacc[2 * kf + 1][3]);
            #pragma unroll
            for (int jj = 0; jj < 8; jj++) {
                uint32_t v4h[4], v4l[4];
                uint32_t vd = vB + (uint32_t)(((kf * 16 + (lane & 7) + (((lane >> 3) & 1) << 3)) * 136
                                              + jj * 16 + ((lane >> 4) << 3)) * 2);
                ldsm4t(vd, v4h);
                ldsm4t(vd + 17408u, v4l);
                #pragma unroll
                for (int t = 0; t < 2; t++) {
                    const int j = 2 * jj + t;
                    mma_bf16(oacc[j], ph, &v4h[2 * t]);
                    mma_bf16(oacc[j], pl, &v4h[2 * t]);
                    mma_bf16(oacc[j], ph, &v4l[2 * t]);
                }
            }
        }
    }

    // ---- finalize: divide by rowsum, write ctx hi/lo ----
    const float i0 = 1.f / rsum[0];
    const float i1 = 1.f / rsum[1];
    const int srow = st * 128 + w * 16 + (lane >> 2);
    #pragma unroll
    for (int j = 0; j < 16; j++) {
        const int col = h * KH + j * 8 + (lane & 3) * 2;
        const long long o0 = ((long long)(b * SS + srow)) * (HH * KH) + col;
        const long long o1 = o0 + (long long)8 * (HH * KH);
        *(uint32_t*)&Ch[o0] = pack_hi(oacc[j][0] * i0, oacc[j][1] * i0);
        *(uint32_t*)&Cl[o0] = pack_lo(oacc[j][0] * i0, oacc[j][1] * i0);
        *(uint32_t*)&Ch[o1] = pack_hi(oacc[j][2] * i1, oacc[j][3] * i1);
        *(uint32_t*)&Cl[o1] = pack_lo(oacc[j][2] * i1, oacc[j][3] * i1);
    }
}

// ---------------- sin/cos table build ----------------
__global__ void build_tab_kernel()
{
    const float LOG2_1E4 = 13.28771238f;
    int i = blockIdx.x * blockDim.x + threadIdx.x;
    const int NQ = SS * (DCQ / 2);
    const int NK = LL * (DC / 2);
    if (i < NQ) {
        int pos = i / (DCQ / 2), f = i % (DCQ / 2);
        float inv = exp2f(-LOG2_1E4 * (float)(2 * f) / (float)DCQ);
        float s, c;
        sincosf((float)pos * inv, &s, &c);
        g_tabq[i] = make_float2(s, c);
    } else if (i < NQ + NK) {
        int k = i - NQ;
        int pos = k / (DC / 2), f = k % (DC / 2);
        float inv = exp2f(-LOG2_1E4 * (float)(2 * f) / (float)DC);
        float s, c;
        sincosf((float)pos * inv, &s, &c);
        g_tabk[k] = make_float2(s, c);
    }
}

// ---------------- fused fp32 -> hi/lo bf16 split ----------------
__device__ __forceinline__ void split4(const float4* __restrict__ in,
                                       uint32_t* __restrict__ hi, uint32_t* __restrict__ lo, int i) {
    float4 v = in[i];
    hi[2 * i]     = pack_hi(v.x, v.y);
    hi[2 * i + 1] = pack_hi(v.z, v.w);
    lo[2 * i]     = pack_lo(v.x, v.y);
    lo[2 * i + 1] = pack_lo(v.z, v.w);
}

#define SZ4_HID   (BB * SS * DIMQ / 4)
#define SZ4_WQ    (HH * KH * DIMQ / 4)
#define SZ4_WKCQ  (HH * KH * DCQ / 4)
#define SZ4_WKCKV (HH * KH * DC / 4)
#define SZ4_WQR   (HH * DCQ * RR / 4)
#define SZ4_WKR   (HH * DC * RR / 4)
#define SZ4_WO    (DIMQ * HH * KH / 4)
#define OFF0 0
#define OFF1 (OFF0 + SZ4_HID)
#define OFF2 (OFF1 + SZ4_WQ)
#define OFF3 (OFF2 + SZ4_WKCQ)
#define OFF4 (OFF3 + SZ4_WKCKV)
#define OFF5 (OFF4 + SZ4_WQR)
#define OFF6 (OFF5 + SZ4_WKR)
#define OFF7 (OFF6 + SZ4_WO)

__global__ void fused_split_kernel(
    const float4* __restrict__ hid, const float4* __restrict__ wq,
    const float4* __restrict__ wkcq, const float4* __restrict__ wkckv,
    const float4* __restrict__ wqr, const float4* __restrict__ wkr,
    const float4* __restrict__ wo,
    uint32_t* __restrict__ hidh, uint32_t* __restrict__ hidl,
    uint32_t* __restrict__ wqh,  uint32_t* __restrict__ wql,
    uint32_t* __restrict__ wkcqh, uint32_t* __restrict__ wkcql,
    uint32_t* __restrict__ wkckvh, uint32_t* __restrict__ wkckvl,
    uint32_t* __restrict__ wqrh, uint32_t* __restrict__ wqrl,
    uint32_t* __restrict__ wkrh, uint32_t* __restrict__ wkrl,
    uint32_t* __restrict__ woh,  uint32_t* __restrict__ wol)
{
    int i = blockIdx.x * blockDim.x + threadIdx.x;
    if (i < OFF1)      split4(hid,   hidh,   hidl,   i - OFF0);
    else if (i < OFF2) split4(wq,    wqh,    wql,    i - OFF1);
    else if (i < OFF3) split4(wkcq,  wkcqh,  wkcql,  i - OFF2);
    else if (i < OFF4) split4(wkckv, wkckvh, wkckvl, i - OFF3);
    else if (i < OFF5) split4(wqr,   wqrh,   wqrl,   i - OFF4);
    else if (i < OFF6) split4(wkr,   wkrh,   wkrl,   i - OFF5);
    else if (i < OFF7) split4(wo,    woh,    wol,    i - OFF6);
}

// ---------------- RoPE (table-based) fused with split ----------------
__global__ void rope_split_kernel(const float* __restrict__ in,
                                  const float2* __restrict__ tab,
                                  uint32_t* __restrict__ oh, uint32_t* __restrict__ ol,
                                  long long total, int dim, int half,
                                  int posDiv, int posMod)
{
    long long t = (long long)blockIdx.x * blockDim.x + threadIdx.x;
    if (t >= total) return;
    const int q  = half >> 1;
    const int pi = (int)(t % q);
    const int j  = pi * 2;
    const long long r = t / q;
    const int pos = (int)((r / posDiv) % posMod);

    const float* p = in + r * (long long)dim;
    float x1a = p[j],        x1b = p[j + 1];
    float x2a = p[j + half], x2b = p[j + half + 1];

    const float2* trow = tab + (long long)pos * (dim / 2);
    float2 sc1 = trow[pi];
    float2 sc2 = trow[pi + dim / 4];

    float oa = x1a * sc1.y - x2a * sc1.x, ob = x1b * sc1.y - x2b * sc1.x;
    float pa = x2a * sc2.y + x1a * sc2.x, pb = x2b * sc2.y + x1b * sc2.x;

    long long b0 = (r * dim + j) >> 1;
    long long b1 = (r * dim + j + half) >> 1;
    oh[b0] = pack_hi(oa, ob);  ol[b0] = pack_lo(oa, ob);
    oh[b1] = pack_hi(pa, pb);  ol[b1] = pack_lo(pa, pb);
}

// ---------------- launch ----------------
static inline void set_smem(const void* fn, int bytes) {
    cudaFuncSetAttribute(fn, cudaFuncAttributeMaxDynamicSharedMemorySize, bytes);
}

#define GETSYM(var, sym) cudaGetSymbolAddress((void**)&var, sym)

extern "C" void kernel_launch(void* const* d_in, const int* in_sizes, int n_in,
                              void* d_out, int out_size)
{
    const float* hidden  = (const float*)d_in[0];
    const float* kv_c    = (const float*)d_in[1];
    const float* Wq      = (const float*)d_in[2];
    const float* w_kc_q  = (const float*)d_in[3];
    const float* w_kc_kv = (const float*)d_in[4];
    const float* W_qr    = (const float*)d_in[5];
    const float* W_kr    = (const float*)d_in[6];
    const float* Wo      = (const float*)d_in[7];
    float* out = (float*)d_out;

    bf16 *hidh, *hidl, *wqh, *wql, *wkcqh, *wkcql, *wkckvh, *wkckvl;
    bf16 *wqrh, *wqrl, *wkrh, *wkrl, *woh, *wol;
    bf16 *qhkh, *qhkl, *qbh, *qbl, *kvrh, *kvrl, *qrh, *qrl, *krh, *krl;
    bf16 *vh, *vl, *ctxh, *ctxl;
    float *qbigf;
    float2 *tabq, *tabk;

    GETSYM(hidh, s_hid_h);     GETSYM(hidl, s_hid_l);
    GETSYM(wqh, s_wq_h);       GETSYM(wql, s_wq_l);
    GETSYM(wkcqh, s_wkcq_h);   GETSYM(wkcql, s_wkcq_l);
    GETSYM(wkckvh, s_wkckv_h); GETSYM(wkckvl, s_wkckv_l);
    GETSYM(wqrh, s_wqr_h);     GETSYM(wqrl, s_wqr_l);
    GETSYM(wkrh, s_wkr_h);     GETSYM(wkrl, s_wkr_l);
    GETSYM(woh, s_wo_h);       GETSYM(wol, s_wo_l);
    GETSYM(qhkh, s_qhk_h);     GETSYM(qhkl, s_qhk_l);
    GETSYM(qbh, s_qbig_h);     GETSYM(qbl, s_qbig_l);
    GETSYM(kvrh, s_kvr_h);     GETSYM(kvrl, s_kvr_l);
    GETSYM(qrh, s_qr_h);       GETSYM(qrl, s_qr_l);
    GETSYM(krh, s_kr_h);       GETSYM(krl, s_kr_l);
    GETSYM(vh, s_v_h);         GETSYM(vl, s_v_l);
    GETSYM(ctxh, s_ctx_h);     GETSYM(ctxl, s_ctx_l);
    GETSYM(qbigf, g_qbig);
    GETSYM(tabq, g_tabq);      GETSYM(tabk, g_tabk);

    const int MS = BB * SS;
    const int SM_T128 = 81920;
    const int SM_F128 = 75776;
    const int SM_F64  = 59392;

    set_smem((const void*)mma_gemm<128, true,  true>,  SM_T128);
    set_smem((const void*)mma_gemm<128, true,  false>, SM_T128);
    set_smem((const void*)mma_gemm<128, false, false>, SM_F128);
    set_smem((const void*)mma_gemm<64,  false, true>,  SM_F64);
    set_smem((const void*)flash_kernel, FL_SMEM);

    // [0] sin/cos tables
    {
        int total = SS * (DCQ / 2) + LL * (DC / 2);
        build_tab_kernel<<<(total + 255) / 256, 256>>>();
    }

    // [1] fused operand split
    fused_split_kernel<<<OFF7 / 256, 256>>>(
        (const float4*)hidden, (const float4*)Wq, (const float4*)w_kc_q,
        (const float4*)w_kc_kv, (const float4*)W_qr, (const float4*)W_kr,
        (const float4*)Wo,
        (uint32_t*)hidh, (uint32_t*)hidl, (uint32_t*)wqh, (uint32_t*)wql,
        (uint32_t*)wkcqh, (uint32_t*)wkcql, (uint32_t*)wkckvh, (uint32_t*)wkckvl,
        (uint32_t*)wqrh, (uint32_t*)wqrl, (uint32_t*)wkrh, (uint32_t*)wkrl,
        (uint32_t*)woh, (uint32_t*)wol);

    // [2] q_hk = hidden @ Wq^T  -> split out
    mma_gemm<128, true, true><<<dim3(DIMQ/128, MS/128, 1), 256, SM_T128>>>(
        hidh, hidl, wqh, wql, nullptr, qhkh, qhkl,
        DIMQ, DIMQ, DIMQ, HH*KH,
        0, 0, 0, 0, 0, 0, 1);

    // [3] q_big = q_hk[h-slice] @ w_kc_q[h]  -> fp32 (pre-RoPE)
    mma_gemm<128, false, false><<<dim3(DCQ/128, MS/128, HH), 256, SM_F128>>>(
        qhkh, qhkl, wkcqh, wkcql, qbigf, nullptr, nullptr,
        KH, HH*KH, DCQ, HH*DCQ,
        0, KH,
        0, (long long)KH*DCQ,
        0, DCQ,
        HH);

    // [4] RoPE+split q_big
    {
        long long total = (long long)BB * SS * HH * (DCQ / 4);
        rope_split_kernel<<<(unsigned)((total + 255) / 256), 256>>>(
            qbigf, tabq, (uint32_t*)qbh, (uint32_t*)qbl, total, DCQ, DCQ/2, HH, SS);
    }
    // [5] RoPE+split kv_c -> kvr
    {
        long long total = (long long)BB * LL * (DC / 4);
        rope_split_kernel<<<(unsigned)((total + 255) / 256), 256>>>(
            kv_c, tabk, (uint32_t*)kvrh, (uint32_t*)kvrl, total, DC, DC/2, 1, LL);
    }

    // [6] V[b,h] = kvr[b] @ w_kc_kv[h]^T  -> split out
    mma_gemm<128, true, true><<<dim3(1, LL/128, BB*HH), 256, SM_T128>>>(
        kvrh, kvrl, wkckvh, wkckvl, nullptr, vh, vl,
        DC, DC, DC, KH,
        (long long)LL*DC, 0,
        0, (long long)KH*DC,
        (long long)HH*LL*KH, (long long)LL*KH,
        HH);

    // [7] q_r = q_big[b,:,h,:] @ W_qr[h]  -> split out
    mma_gemm<64, false, true><<<dim3(1, SS/128, BB*HH), 256, SM_F64>>>(
        qbh, qbl, wqrh, wqrl, nullptr, qrh, qrl,
        DCQ, HH*DCQ, RR, RR,
        (long long)SS*HH*DCQ, DCQ,
        0, (long long)DCQ*RR,
        (long long)HH*SS*RR, (long long)SS*RR,
        HH);

    // [8] k_r = kvr[b] @ W_kr[h]  -> split out
    mma_gemm<64, false, true><<<dim3(1, LL/128, BB*HH), 256, SM_F64>>>(
        kvrh, kvrl, wkrh, wkrl, nullptr, krh, krl,
        DC, DC, RR, RR,
        (long long)LL*DC, 0,
        0, (long long)DC*RR,
        (long long)HH*LL*RR, (long long)LL*RR,
        HH);

    // [9] flash: scores + softmax + attn@V  -> ctx hi/lo
    flash_kernel<<<dim3(SS/128, BB*HH), 256, FL_SMEM>>>(
        qrh, qrl, krh, krl, vh, vl, ctxh, ctxl);

    // [10] out = ctx @ Wo^T  -> fp32 final
    mma_gemm<128, true, false><<<dim3(DIMQ/128, MS/128, 1), 256, SM_T128>>>(
        ctxh, ctxl, woh, wol, out, nullptr, nullptr,
        HH*KH, HH*KH, HH*KH, DIMQ,
        0, 0, 0, 0, 0, 0, 1);
}